// round 1
// baseline (speedup 1.0000x reference)
#include <cuda_runtime.h>

#define ND_MAX 50000
#define NE_MAX 640000
#define DD 128
#define TILE_ROWS 16
#define GEMM_THREADS 128
#define GEMM_SMEM ((DD*DD + TILE_ROWS*DD) * (int)sizeof(float))  // 64KB + 8KB

// ---- scratch (no allocation allowed; static device globals) ----
__device__ float g_agg[ND_MAX * DD];
__device__ float g_buf0[ND_MAX * DD];
__device__ float g_buf1[ND_MAX * DD];
__device__ float g_deg[2 * ND_MAX];      // [0..N): deg_out, [ND_MAX..): deg_in
__device__ float g_inv_out[ND_MAX];
__device__ float g_inv_in[ND_MAX];

// ---------------------------------------------------------------
__global__ void zero_degs_kernel(int n) {
    int i = blockIdx.x * blockDim.x + threadIdx.x;
    if (i < n) { g_deg[i] = 0.f; g_deg[ND_MAX + i] = 0.f; }
}

__global__ void deg_kernel(const int* __restrict__ src, const int* __restrict__ dst, int e) {
    int i = blockIdx.x * blockDim.x + threadIdx.x;
    if (i < e) {
        atomicAdd(&g_deg[src[i]], 1.f);
        atomicAdd(&g_deg[ND_MAX + dst[i]], 1.f);
    }
}

__global__ void inv_kernel(int n) {
    int i = blockIdx.x * blockDim.x + threadIdx.x;
    if (i < n) {
        g_inv_out[i] = rsqrtf(fmaxf(g_deg[i], 1.f));
        g_inv_in[i]  = rsqrtf(fmaxf(g_deg[ND_MAX + i], 1.f));
    }
}

__global__ void zero_agg_kernel(int n4) {
    int i = blockIdx.x * blockDim.x + threadIdx.x;
    if (i < n4) reinterpret_cast<float4*>(g_agg)[i] = make_float4(0.f, 0.f, 0.f, 0.f);
}

// One warp per edge. Lane moves one float4 (4 cols). Gather x[src]*inv_out[src],
// vector-RED into g_agg[dst]. src/dst/inv loads are warp-uniform (broadcast).
__global__ void scatter_kernel(const float* __restrict__ x,
                               const int* __restrict__ src,
                               const int* __restrict__ dst, int e) {
    int gid  = blockIdx.x * blockDim.x + threadIdx.x;
    int eid  = gid >> 5;
    if (eid >= e) return;
    int lane = gid & 31;

    int s = src[eid];
    int d = dst[eid];
    float sc = g_inv_out[s];

    float4 v = reinterpret_cast<const float4*>(x + (size_t)s * DD)[lane];
    v.x *= sc; v.y *= sc; v.z *= sc; v.w *= sc;

    float4* ap = reinterpret_cast<float4*>(g_agg + (size_t)d * DD) + lane;
    asm volatile("red.global.add.v4.f32 [%0], {%1,%2,%3,%4};"
                 :: "l"(ap), "f"(v.x), "f"(v.y), "f"(v.z), "f"(v.w)
                 : "memory");
}

// out[r,:] = relu( (g_agg[r,:] * inv_in[r]) @ W + b )
// Block = 128 threads (4 warps). Block tile = 16 rows; warp owns 4 rows,
// lane owns 4 consecutive cols (float4). W resident in SMEM (64KB).
__global__ void gemm_relu_kernel(const float* __restrict__ W,
                                 const float* __restrict__ bias,
                                 float* __restrict__ out, int n) {
    extern __shared__ float sm[];
    float* Wsm = sm;                 // DD*DD
    float* Asm = sm + DD * DD;       // TILE_ROWS*DD

    int tid  = threadIdx.x;          // 0..127
    int lane = tid & 31;
    int warp = tid >> 5;             // 0..3

    for (int i = tid; i < DD * DD; i += GEMM_THREADS) Wsm[i] = W[i];
    float4 bv = reinterpret_cast<const float4*>(bias)[lane];

    for (int r0 = blockIdx.x * TILE_ROWS; r0 < n; r0 += gridDim.x * TILE_ROWS) {
        __syncthreads();  // protect Asm reuse (also orders Wsm on first pass)
        #pragma unroll
        for (int rr = 0; rr < TILE_ROWS; rr++) {
            int row = r0 + rr;
            float a = 0.f;
            if (row < n) a = g_agg[(size_t)row * DD + tid] * g_inv_in[row];
            Asm[rr * DD + tid] = a;
        }
        __syncthreads();

        const float* a0 = Asm + (4 * warp + 0) * DD;
        const float* a1 = Asm + (4 * warp + 1) * DD;
        const float* a2 = Asm + (4 * warp + 2) * DD;
        const float* a3 = Asm + (4 * warp + 3) * DD;

        float4 acc0 = {0,0,0,0}, acc1 = {0,0,0,0}, acc2 = {0,0,0,0}, acc3 = {0,0,0,0};

        #pragma unroll 8
        for (int k = 0; k < DD; k++) {
            float4 w = *reinterpret_cast<const float4*>(&Wsm[k * DD + 4 * lane]);
            float v0 = a0[k], v1 = a1[k], v2 = a2[k], v3 = a3[k];
            acc0.x += v0 * w.x; acc0.y += v0 * w.y; acc0.z += v0 * w.z; acc0.w += v0 * w.w;
            acc1.x += v1 * w.x; acc1.y += v1 * w.y; acc1.z += v1 * w.z; acc1.w += v1 * w.w;
            acc2.x += v2 * w.x; acc2.y += v2 * w.y; acc2.z += v2 * w.z; acc2.w += v2 * w.w;
            acc3.x += v3 * w.x; acc3.y += v3 * w.y; acc3.z += v3 * w.z; acc3.w += v3 * w.w;
        }

        int rbase = r0 + 4 * warp;
        float4 o;
        if (rbase + 0 < n) {
            o.x = fmaxf(acc0.x + bv.x, 0.f); o.y = fmaxf(acc0.y + bv.y, 0.f);
            o.z = fmaxf(acc0.z + bv.z, 0.f); o.w = fmaxf(acc0.w + bv.w, 0.f);
            reinterpret_cast<float4*>(out + (size_t)(rbase + 0) * DD)[lane] = o;
        }
        if (rbase + 1 < n) {
            o.x = fmaxf(acc1.x + bv.x, 0.f); o.y = fmaxf(acc1.y + bv.y, 0.f);
            o.z = fmaxf(acc1.z + bv.z, 0.f); o.w = fmaxf(acc1.w + bv.w, 0.f);
            reinterpret_cast<float4*>(out + (size_t)(rbase + 1) * DD)[lane] = o;
        }
        if (rbase + 2 < n) {
            o.x = fmaxf(acc2.x + bv.x, 0.f); o.y = fmaxf(acc2.y + bv.y, 0.f);
            o.z = fmaxf(acc2.z + bv.z, 0.f); o.w = fmaxf(acc2.w + bv.w, 0.f);
            reinterpret_cast<float4*>(out + (size_t)(rbase + 2) * DD)[lane] = o;
        }
        if (rbase + 3 < n) {
            o.x = fmaxf(acc3.x + bv.x, 0.f); o.y = fmaxf(acc3.y + bv.y, 0.f);
            o.z = fmaxf(acc3.z + bv.z, 0.f); o.w = fmaxf(acc3.w + bv.w, 0.f);
            reinterpret_cast<float4*>(out + (size_t)(rbase + 3) * DD)[lane] = o;
        }
    }
}

// ---------------------------------------------------------------
extern "C" void kernel_launch(void* const* d_in, const int* in_sizes, int n_in,
                              void* d_out, int out_size) {
    const float* x   = (const float*)d_in[0];
    const float* Ws  = (const float*)d_in[1];
    const float* bs  = (const float*)d_in[2];
    const int*   src = (const int*)d_in[3];
    const int*   dst = (const int*)d_in[4];
    float* out = (float*)d_out;

    int n = in_sizes[0] / DD;
    int e = in_sizes[3];
    int L = in_sizes[1] / (DD * DD);

    float *buf0, *buf1;
    cudaGetSymbolAddress((void**)&buf0, g_buf0);
    cudaGetSymbolAddress((void**)&buf1, g_buf1);

    cudaFuncSetAttribute(gemm_relu_kernel,
                         cudaFuncAttributeMaxDynamicSharedMemorySize, GEMM_SMEM);

    // degree setup (once per launch, reused by all layers)
    zero_degs_kernel<<<(n + 255) / 256, 256>>>(n);
    deg_kernel<<<(e + 255) / 256, 256>>>(src, dst, e);
    inv_kernel<<<(n + 255) / 256, 256>>>(n);

    int n4 = n * DD / 4;
    long sth = (long)e * 32;
    int scatter_blocks = (int)((sth + 255) / 256);
    int gemm_blocks = (n + TILE_ROWS - 1) / TILE_ROWS;

    const float* cur = x;
    for (int l = 0; l < L; l++) {
        zero_agg_kernel<<<(n4 + 255) / 256, 256>>>(n4);
        scatter_kernel<<<scatter_blocks, 256>>>(cur, src, dst, e);
        float* o = (l == L - 1) ? out : ((l & 1) == 0 ? buf0 : buf1);
        gemm_relu_kernel<<<gemm_blocks, GEMM_THREADS, GEMM_SMEM>>>(
            Ws + (size_t)l * DD * DD, bs + (size_t)l * DD, o, n);
        cur = o;
    }
}

// round 2
// speedup vs baseline: 1.3296x; 1.3296x over previous
#include <cuda_runtime.h>

#define ND_MAX 50000
#define NE_MAX 640000
#define DD 128
#define TILE_ROWS 16
#define GEMM_THREADS 128
#define GEMM_SMEM ((DD*DD + TILE_ROWS*DD) * (int)sizeof(float))  // 64KB + 8KB
#define SCAN_B 256

// ---- scratch (no allocation allowed; static device globals) ----
__device__ float g_agg[ND_MAX * DD];
__device__ float g_buf0[ND_MAX * DD];
__device__ float g_buf1[ND_MAX * DD];
__device__ int   g_cnt_out[ND_MAX];
__device__ int   g_cnt_in[ND_MAX];
__device__ int   g_start[ND_MAX];     // CSR row start (exclusive scan of cnt_in)
__device__ int   g_incl[ND_MAX];      // block-local inclusive scan temp
__device__ int   g_bsum[SCAN_B];      // per-block sums (needs ceil(N/256) <= 256)
__device__ int   g_fill[ND_MAX];
__device__ int   g_csr_src[NE_MAX];
__device__ float g_inv_out[ND_MAX];
__device__ float g_inv_in[ND_MAX];

// ---------------------------------------------------------------
__global__ void zero_setup_kernel(int n) {
    int i = blockIdx.x * blockDim.x + threadIdx.x;
    if (i < n) { g_cnt_out[i] = 0; g_cnt_in[i] = 0; g_fill[i] = 0; }
}

__global__ void count_kernel(const int* __restrict__ src, const int* __restrict__ dst, int e) {
    int i = blockIdx.x * blockDim.x + threadIdx.x;
    if (i < e) {
        atomicAdd(&g_cnt_out[src[i]], 1);
        atomicAdd(&g_cnt_in[dst[i]], 1);
    }
}

__global__ void inv_kernel(int n) {
    int i = blockIdx.x * blockDim.x + threadIdx.x;
    if (i < n) {
        g_inv_out[i] = rsqrtf((float)max(g_cnt_out[i], 1));
        g_inv_in[i]  = rsqrtf((float)max(g_cnt_in[i], 1));
    }
}

// --- 3-phase exclusive scan of g_cnt_in -> g_start ---
__global__ void scan1_kernel(int n) {
    __shared__ int sm[SCAN_B];
    int i = blockIdx.x * SCAN_B + threadIdx.x;
    int v = (i < n) ? g_cnt_in[i] : 0;
    sm[threadIdx.x] = v;
    __syncthreads();
    for (int off = 1; off < SCAN_B; off <<= 1) {
        int t = (threadIdx.x >= off) ? sm[threadIdx.x - off] : 0;
        __syncthreads();
        sm[threadIdx.x] += t;
        __syncthreads();
    }
    if (i < n) g_incl[i] = sm[threadIdx.x];
    if (threadIdx.x == SCAN_B - 1) g_bsum[blockIdx.x] = sm[SCAN_B - 1];
}

__global__ void scan2_kernel(int nb) {  // single block
    __shared__ int sm[SCAN_B];
    int v = (threadIdx.x < nb) ? g_bsum[threadIdx.x] : 0;
    sm[threadIdx.x] = v;
    __syncthreads();
    for (int off = 1; off < SCAN_B; off <<= 1) {
        int t = (threadIdx.x >= off) ? sm[threadIdx.x - off] : 0;
        __syncthreads();
        sm[threadIdx.x] += t;
        __syncthreads();
    }
    if (threadIdx.x < nb) g_bsum[threadIdx.x] = sm[threadIdx.x];
}

__global__ void scan3_kernel(int n) {
    int i = blockIdx.x * SCAN_B + threadIdx.x;
    if (i < n) {
        int off = (blockIdx.x > 0) ? g_bsum[blockIdx.x - 1] : 0;
        g_start[i] = off + g_incl[i] - g_cnt_in[i];
    }
}

__global__ void fill_kernel(const int* __restrict__ src, const int* __restrict__ dst, int e) {
    int i = blockIdx.x * blockDim.x + threadIdx.x;
    if (i < e) {
        int d = dst[i];
        int pos = g_start[d] + atomicAdd(&g_fill[d], 1);
        g_csr_src[pos] = src[i];
    }
}

// --- aggregation: one warp per dst node, lane owns one float4 (4 cols) ---
// g_agg[d,:] = inv_in[d] * sum_{s in in(d)} x[s,:] * inv_out[s]
__global__ void gather_kernel(const float* __restrict__ x, int n) {
    int gid  = blockIdx.x * blockDim.x + threadIdx.x;
    int node = gid >> 5;
    if (node >= n) return;
    int lane = gid & 31;

    int start = g_start[node];
    int cnt   = g_cnt_in[node];

    float4 acc = make_float4(0.f, 0.f, 0.f, 0.f);
    for (int j = 0; j < cnt; j++) {
        int s = __ldg(&g_csr_src[start + j]);       // warp-uniform broadcast
        float sc = __ldg(&g_inv_out[s]);
        float4 v = reinterpret_cast<const float4*>(x + (size_t)s * DD)[lane];
        acc.x += v.x * sc; acc.y += v.y * sc; acc.z += v.z * sc; acc.w += v.w * sc;
    }
    float si = g_inv_in[node];
    acc.x *= si; acc.y *= si; acc.z *= si; acc.w *= si;
    reinterpret_cast<float4*>(g_agg + (size_t)node * DD)[lane] = acc;
}

// out[r,:] = relu( g_agg[r,:] @ W + b )
// Block = 128 threads (4 warps). Block tile = 16 rows; warp owns 4 rows,
// lane owns 4 consecutive cols (float4). W resident in SMEM (64KB).
__global__ void gemm_relu_kernel(const float* __restrict__ W,
                                 const float* __restrict__ bias,
                                 float* __restrict__ out, int n) {
    extern __shared__ float sm[];
    float* Wsm = sm;                 // DD*DD
    float* Asm = sm + DD * DD;       // TILE_ROWS*DD

    int tid  = threadIdx.x;          // 0..127
    int lane = tid & 31;
    int warp = tid >> 5;             // 0..3

    for (int i = tid; i < DD * DD; i += GEMM_THREADS) Wsm[i] = W[i];
    float4 bv = reinterpret_cast<const float4*>(bias)[lane];

    for (int r0 = blockIdx.x * TILE_ROWS; r0 < n; r0 += gridDim.x * TILE_ROWS) {
        __syncthreads();  // protect Asm reuse (also orders Wsm on first pass)
        #pragma unroll
        for (int rr = 0; rr < TILE_ROWS; rr++) {
            int row = r0 + rr;
            float a = 0.f;
            if (row < n) a = g_agg[(size_t)row * DD + tid];
            Asm[rr * DD + tid] = a;
        }
        __syncthreads();

        const float* a0 = Asm + (4 * warp + 0) * DD;
        const float* a1 = Asm + (4 * warp + 1) * DD;
        const float* a2 = Asm + (4 * warp + 2) * DD;
        const float* a3 = Asm + (4 * warp + 3) * DD;

        float4 acc0 = {0,0,0,0}, acc1 = {0,0,0,0}, acc2 = {0,0,0,0}, acc3 = {0,0,0,0};

        #pragma unroll 8
        for (int k = 0; k < DD; k++) {
            float4 w = *reinterpret_cast<const float4*>(&Wsm[k * DD + 4 * lane]);
            float v0 = a0[k], v1 = a1[k], v2 = a2[k], v3 = a3[k];
            acc0.x += v0 * w.x; acc0.y += v0 * w.y; acc0.z += v0 * w.z; acc0.w += v0 * w.w;
            acc1.x += v1 * w.x; acc1.y += v1 * w.y; acc1.z += v1 * w.z; acc1.w += v1 * w.w;
            acc2.x += v2 * w.x; acc2.y += v2 * w.y; acc2.z += v2 * w.z; acc2.w += v2 * w.w;
            acc3.x += v3 * w.x; acc3.y += v3 * w.y; acc3.z += v3 * w.z; acc3.w += v3 * w.w;
        }

        int rbase = r0 + 4 * warp;
        float4 o;
        if (rbase + 0 < n) {
            o.x = fmaxf(acc0.x + bv.x, 0.f); o.y = fmaxf(acc0.y + bv.y, 0.f);
            o.z = fmaxf(acc0.z + bv.z, 0.f); o.w = fmaxf(acc0.w + bv.w, 0.f);
            reinterpret_cast<float4*>(out + (size_t)(rbase + 0) * DD)[lane] = o;
        }
        if (rbase + 1 < n) {
            o.x = fmaxf(acc1.x + bv.x, 0.f); o.y = fmaxf(acc1.y + bv.y, 0.f);
            o.z = fmaxf(acc1.z + bv.z, 0.f); o.w = fmaxf(acc1.w + bv.w, 0.f);
            reinterpret_cast<float4*>(out + (size_t)(rbase + 1) * DD)[lane] = o;
        }
        if (rbase + 2 < n) {
            o.x = fmaxf(acc2.x + bv.x, 0.f); o.y = fmaxf(acc2.y + bv.y, 0.f);
            o.z = fmaxf(acc2.z + bv.z, 0.f); o.w = fmaxf(acc2.w + bv.w, 0.f);
            reinterpret_cast<float4*>(out + (size_t)(rbase + 2) * DD)[lane] = o;
        }
        if (rbase + 3 < n) {
            o.x = fmaxf(acc3.x + bv.x, 0.f); o.y = fmaxf(acc3.y + bv.y, 0.f);
            o.z = fmaxf(acc3.z + bv.z, 0.f); o.w = fmaxf(acc3.w + bv.w, 0.f);
            reinterpret_cast<float4*>(out + (size_t)(rbase + 3) * DD)[lane] = o;
        }
    }
}

// ---------------------------------------------------------------
extern "C" void kernel_launch(void* const* d_in, const int* in_sizes, int n_in,
                              void* d_out, int out_size) {
    const float* x   = (const float*)d_in[0];
    const float* Ws  = (const float*)d_in[1];
    const float* bs  = (const float*)d_in[2];
    const int*   src = (const int*)d_in[3];
    const int*   dst = (const int*)d_in[4];
    float* out = (float*)d_out;

    int n = in_sizes[0] / DD;
    int e = in_sizes[3];
    int L = in_sizes[1] / (DD * DD);

    float *buf0, *buf1;
    cudaGetSymbolAddress((void**)&buf0, g_buf0);
    cudaGetSymbolAddress((void**)&buf1, g_buf1);

    cudaFuncSetAttribute(gemm_relu_kernel,
                         cudaFuncAttributeMaxDynamicSharedMemorySize, GEMM_SMEM);

    int nbN = (n + 255) / 256;
    int nbE = (e + 255) / 256;
    int nbScan = (n + SCAN_B - 1) / SCAN_B;

    // ---- CSR build + degree setup (once per launch, reused by all layers)
    zero_setup_kernel<<<nbN, 256>>>(n);
    count_kernel<<<nbE, 256>>>(src, dst, e);
    inv_kernel<<<nbN, 256>>>(n);
    scan1_kernel<<<nbScan, SCAN_B>>>(n);
    scan2_kernel<<<1, SCAN_B>>>(nbScan);
    scan3_kernel<<<nbScan, SCAN_B>>>(n);
    fill_kernel<<<nbE, 256>>>(src, dst, e);

    long gth = (long)n * 32;
    int gather_blocks = (int)((gth + 255) / 256);
    int gemm_blocks = (n + TILE_ROWS - 1) / TILE_ROWS;

    const float* cur = x;
    for (int l = 0; l < L; l++) {
        gather_kernel<<<gather_blocks, 256>>>(cur, n);
        float* o = (l == L - 1) ? out : ((l & 1) == 0 ? buf0 : buf1);
        gemm_relu_kernel<<<gemm_blocks, GEMM_THREADS, GEMM_SMEM>>>(
            Ws + (size_t)l * DD * DD, bs + (size_t)l * DD, o, n);
        cur = o;
    }
}